// round 11
// baseline (speedup 1.0000x reference)
#include <cuda_runtime.h>
#include <math.h>

// Problem constants (fixed by reference setup_inputs)
#define N_BATCH 256
#define M_ROWS  8
#define T_LEN   16384
#define THREADS 256
#define NWARPS  (THREADS / 32)
#define T4      (T_LEN / 4)              // 4096 float4 per row
#define SPLITS  4                        // CTAs per batch
#define UNIT_T4 (T4 / SPLITS)            // 1024 float4 columns per CTA
#define CHUNKS  2                        // 16 LDG.128 per iteration
#define ITERS   (UNIT_T4 / (THREADS * CHUNKS))   // 2
#define NACC    30                       // band |m-k| <= 4 of the 8x8 Gram

// band layout: acc[c_off(d) + k] holds sum_t X[k+d][t] * X[k][t]
__host__ __device__ __forceinline__ constexpr int c_off(int d) {
    return (d == 0) ? 0 : (d == 1) ? 8 : (d == 2) ? 15 : (d == 3) ? 21 : 26;
}

// Cross-CTA scratch (static device globals; zero-init; no allocation)
__device__ float        g_part[N_BATCH * SPLITS * NACC];
__device__ unsigned int g_cnt[N_BATCH];    // reset by finalizer each replay

__global__ void __launch_bounds__(THREADS, 3)
ssf_kernel(const float* __restrict__ X, float* __restrict__ out) {
    __shared__ float sred[NWARPS][NACC];
    __shared__ float sC[NACC];
    __shared__ int   s_fin;

    const int n   = blockIdx.x >> 2;     // batch
    const int s   = blockIdx.x & 3;      // split
    const int tid = threadIdx.x;

    const float4* __restrict__ base =
        reinterpret_cast<const float4*>(X + (size_t)n * M_ROWS * T_LEN);

    float acc[NACC];
#pragma unroll
    for (int i = 0; i < NACC; i++) acc[i] = 0.f;

#pragma unroll
    for (int it = 0; it < ITERS; it++) {
        const int t4a = s * UNIT_T4 + it * (THREADS * CHUNKS) + tid;
        const int t4b = t4a + THREADS;

        // 16 LDG.128 issued back-to-back (R8-proven shape)
        float4 va[M_ROWS], vb[M_ROWS];
#pragma unroll
        for (int m = 0; m < M_ROWS; m++)
            va[m] = base[m * T4 + t4a];
#pragma unroll
        for (int m = 0; m < M_ROWS; m++)
            vb[m] = base[m * T4 + t4b];

        // banded dense FMA block (only |m-k| <= 4 pairs are ever used)
#pragma unroll
        for (int m = 0; m < M_ROWS; m++) {
            const int dmax = (m < 4) ? m : 4;
#pragma unroll
            for (int d = 0; d <= dmax; d++) {
                const int ai = c_off(d) + (m - d);
                acc[ai] = fmaf(va[m].x, va[m - d].x, acc[ai]);
                acc[ai] = fmaf(va[m].y, va[m - d].y, acc[ai]);
                acc[ai] = fmaf(va[m].z, va[m - d].z, acc[ai]);
                acc[ai] = fmaf(va[m].w, va[m - d].w, acc[ai]);
                acc[ai] = fmaf(vb[m].x, vb[m - d].x, acc[ai]);
                acc[ai] = fmaf(vb[m].y, vb[m - d].y, acc[ai]);
                acc[ai] = fmaf(vb[m].z, vb[m - d].z, acc[ai]);
                acc[ai] = fmaf(vb[m].w, vb[m - d].w, acc[ai]);
            }
        }
    }

    // ---- CTA reduce of the 30 banded sums ----
#pragma unroll
    for (int i = 0; i < NACC; i++) {
#pragma unroll
        for (int off = 16; off > 0; off >>= 1)
            acc[i] += __shfl_down_sync(0xffffffffu, acc[i], off);
    }

    const int warp = tid >> 5;
    const int lane = tid & 31;
    if (lane == 0) {
#pragma unroll
        for (int i = 0; i < NACC; i++) sred[warp][i] = acc[i];
    }
    __syncthreads();

    if (tid < NACC) {
        float v = 0.f;
#pragma unroll
        for (int w = 0; w < NWARPS; w++) v += sred[w][tid];
        g_part[(n * SPLITS + s) * NACC + tid] = v * (1.0f / (float)T_LEN);
        __threadfence();
    }
    __syncthreads();

    if (tid == 0) {
        const unsigned int old = atomicAdd(&g_cnt[n], 1u);
        s_fin = (old == SPLITS - 1) ? 1 : 0;
    }
    __syncthreads();
    if (!s_fin) return;

    // ---- last CTA of this batch finalizes (deterministic fixed order) ----
    if (tid < NACC) {
        float v = 0.f;
#pragma unroll
        for (int sp = 0; sp < SPLITS; sp++) {
            const volatile float* p =
                (const volatile float*)&g_part[(n * SPLITS + sp) * NACC + tid];
            v += *p;
        }
        sC[tid] = v;     // banded C (already /T)
    }
    __syncthreads();

    if (tid == 0) {
        // tri(s1,s2) = 1/4 * sum_j C[j+s2][j+s1] = 1/4 * sum_j band[d][j+s1],
        // d = s2-s1, in jnp.triu_indices(5) row-major order.
        float tri[15];
        int p = 0;
#pragma unroll
        for (int s1 = 0; s1 < 5; s1++) {
#pragma unroll
            for (int s2 = s1; s2 < 5; s2++) {
                const int d = s2 - s1;
                float r = 0.f;
#pragma unroll
                for (int j = 0; j < 4; j++)
                    r += sC[c_off(d) + j + s1];
                tri[p++] = r * 0.25f;
            }
        }

        // feat = [tri (15), zeros (15)]; standardize over all 30 (pop. std)
        float mean = 0.f;
#pragma unroll
        for (int i = 0; i < 15; i++) mean += tri[i];
        mean *= (1.0f / 30.0f);

        float var = 0.f;
#pragma unroll
        for (int i = 0; i < 15; i++) {
            const float dd = tri[i] - mean;
            var += dd * dd;
        }
        var += 15.0f * mean * mean;    // 15 zero entries contribute mean^2
        var *= (1.0f / 30.0f);

        const float inv = 1.0f / (sqrtf(var) + 1e-8f);

        float* o = out + n * 30;
#pragma unroll
        for (int i = 0; i < 15; i++) o[i] = (tri[i] - mean) * inv;
        const float zval = -mean * inv;
#pragma unroll
        for (int i = 15; i < 30; i++) o[i] = zval;

        atomicExch(&g_cnt[n], 0u);     // reset for next graph replay
    }
}

extern "C" void kernel_launch(void* const* d_in, const int* in_sizes, int n_in,
                              void* d_out, int out_size) {
    const float* X = (const float*)d_in[0];
    float* out = (float*)d_out;
    ssf_kernel<<<N_BATCH * SPLITS, THREADS>>>(X, out);
}

// round 12
// speedup vs baseline: 1.0857x; 1.0857x over previous
#include <cuda_runtime.h>
#include <math.h>
#include <stdint.h>

// Problem constants (fixed by reference setup_inputs)
#define N_BATCH 256
#define M_ROWS  8
#define T_LEN   16384
#define NPAIRS  36               // 8*9/2 lower-tri (symmetric Gram)
#define THREADS 256
#define NWARPS  (THREADS / 32)
#define STAGE_FLOATS 1024        // t-columns per stage
#define STAGE_ROW_BYTES (STAGE_FLOATS * 4)          // 4096 B per row
#define STAGE_BYTES (M_ROWS * STAGE_ROW_BYTES)      // 32 KB per stage
#define NSTAGES 3
#define ITERS   (T_LEN / STAGE_FLOATS)              // 16

__device__ __forceinline__ uint32_t smem_u32(const void* p) {
    return (uint32_t)__cvta_generic_to_shared(p);
}

__device__ __forceinline__ void mbar_init(uint32_t mbar, uint32_t count) {
    asm volatile("mbarrier.init.shared.b64 [%0], %1;" :: "r"(mbar), "r"(count) : "memory");
}
__device__ __forceinline__ void mbar_arrive(uint32_t mbar) {
    asm volatile("mbarrier.arrive.shared.b64 _, [%0];" :: "r"(mbar) : "memory");
}
__device__ __forceinline__ void mbar_arrive_expect_tx(uint32_t mbar, uint32_t bytes) {
    asm volatile("mbarrier.arrive.expect_tx.shared.b64 _, [%0], %1;"
                 :: "r"(mbar), "r"(bytes) : "memory");
}
__device__ __forceinline__ void mbar_wait(uint32_t mbar, uint32_t parity) {
    asm volatile(
        "{\n\t.reg .pred P;\n"
        "W%=:\n\t"
        "mbarrier.try_wait.parity.acquire.cta.shared::cta.b64 P, [%0], %1, 0x989680;\n\t"
        "@!P bra W%=;\n\t}"
        :: "r"(mbar), "r"(parity) : "memory");
}
__device__ __forceinline__ void bulk_g2s(uint32_t dst, const void* src,
                                         uint32_t bytes, uint32_t mbar) {
    asm volatile(
        "cp.async.bulk.shared::cluster.global.mbarrier::complete_tx::bytes "
        "[%0], [%1], %2, [%3];"
        :: "r"(dst), "l"(src), "r"(bytes), "r"(mbar) : "memory");
}

__device__ __forceinline__ int cidx(int a, int b) {
    const int m = a > b ? a : b;
    const int k = a > b ? b : a;
    return m * (m + 1) / 2 + k;
}

extern __shared__ float4 s_tiles[];   // [NSTAGES][M_ROWS][STAGE_FLOATS/4]

__global__ void __launch_bounds__(THREADS)
ssf_tma_kernel(const float* __restrict__ X, float* __restrict__ out) {
    __shared__ __align__(8) unsigned long long s_full[NSTAGES];
    __shared__ __align__(8) unsigned long long s_empty[NSTAGES];
    __shared__ float sred[NWARPS][NPAIRS];
    __shared__ float sC[NPAIRS];

    const int n   = blockIdx.x;
    const int tid = threadIdx.x;

    const char* __restrict__ gbase =
        (const char*)(X + (size_t)n * M_ROWS * T_LEN);

    uint32_t full[NSTAGES], empty[NSTAGES];
#pragma unroll
    for (int s = 0; s < NSTAGES; s++) {
        full[s]  = smem_u32(&s_full[s]);
        empty[s] = smem_u32(&s_empty[s]);
    }
    const uint32_t tiles_base = smem_u32(&s_tiles[0]);

    if (tid == 0) {
#pragma unroll
        for (int s = 0; s < NSTAGES; s++) {
            mbar_init(full[s],  1);        // completes via tx-bytes
            mbar_init(empty[s], THREADS);  // all threads arrive after consuming
        }
    }
    __syncthreads();

    // ---- prologue: issue stages 0..NSTAGES-1 ----
    if (tid == 0) {
#pragma unroll
        for (int s = 0; s < NSTAGES; s++) {
            mbar_arrive_expect_tx(full[s], STAGE_BYTES);
#pragma unroll
            for (int r = 0; r < M_ROWS; r++)
                bulk_g2s(tiles_base + s * STAGE_BYTES + r * STAGE_ROW_BYTES,
                         gbase + (size_t)r * T_LEN * 4 + (size_t)s * STAGE_ROW_BYTES,
                         STAGE_ROW_BYTES, full[s]);
        }
    }

    float acc[NPAIRS];
#pragma unroll
    for (int i = 0; i < NPAIRS; i++) acc[i] = 0.f;

#pragma unroll 1
    for (int it = 0; it < ITERS; it++) {
        const int slot = it % NSTAGES;
        const uint32_t parity = (uint32_t)((it / NSTAGES) & 1);

        mbar_wait(full[slot], parity);

        // each thread owns float4-column `tid` of this stage
        const float4* tile = s_tiles + (size_t)slot * (STAGE_BYTES / 16) + tid;
        float4 v[M_ROWS];
#pragma unroll
        for (int m = 0; m < M_ROWS; m++)
            v[m] = tile[m * (STAGE_FLOATS / 4)];     // conflict-free LDS.128

        int idx = 0;
#pragma unroll
        for (int m = 0; m < M_ROWS; m++) {
#pragma unroll
            for (int k = 0; k <= m; k++) {
                acc[idx] = fmaf(v[m].x, v[k].x, acc[idx]);
                acc[idx] = fmaf(v[m].y, v[k].y, acc[idx]);
                acc[idx] = fmaf(v[m].z, v[k].z, acc[idx]);
                acc[idx] = fmaf(v[m].w, v[k].w, acc[idx]);
                idx++;
            }
        }

        mbar_arrive(empty[slot]);   // this thread is done with the slot

        // producer: refill this slot with stage it+NSTAGES
        const int j = it + NSTAGES;
        if (tid == 0 && j < ITERS) {
            mbar_wait(empty[slot], parity);   // all 256 consumers released it
            mbar_arrive_expect_tx(full[slot], STAGE_BYTES);
#pragma unroll
            for (int r = 0; r < M_ROWS; r++)
                bulk_g2s(tiles_base + slot * STAGE_BYTES + r * STAGE_ROW_BYTES,
                         gbase + (size_t)r * T_LEN * 4 + (size_t)j * STAGE_ROW_BYTES,
                         STAGE_ROW_BYTES, full[slot]);
        }
    }

    // ---- CTA reduce of the 36 sums ----
#pragma unroll
    for (int i = 0; i < NPAIRS; i++) {
#pragma unroll
        for (int off = 16; off > 0; off >>= 1)
            acc[i] += __shfl_down_sync(0xffffffffu, acc[i], off);
    }
    const int warp = tid >> 5;
    const int lane = tid & 31;
    if (lane == 0) {
#pragma unroll
        for (int i = 0; i < NPAIRS; i++) sred[warp][i] = acc[i];
    }
    __syncthreads();

    if (tid < NPAIRS) {
        float s = 0.f;
#pragma unroll
        for (int w = 0; w < NWARPS; w++) s += sred[w][tid];
        sC[tid] = s * (1.0f / (float)T_LEN);   // C = Gram / T
    }
    __syncthreads();

    if (tid == 0) {
        // R[s1][s2] = mean_j C[j+s1][j+s2]; triu_indices(5) row-major order.
        float tri[15];
        int p = 0;
#pragma unroll
        for (int s1 = 0; s1 < 5; s1++) {
#pragma unroll
            for (int s2 = s1; s2 < 5; s2++) {
                float r = 0.f;
#pragma unroll
                for (int j = 0; j < 4; j++)
                    r += sC[cidx(j + s1, j + s2)];
                tri[p++] = r * 0.25f;
            }
        }

        // feat = [tri (15), zeros (15)]; standardize over all 30 (pop. std)
        float mean = 0.f;
#pragma unroll
        for (int i = 0; i < 15; i++) mean += tri[i];
        mean *= (1.0f / 30.0f);

        float var = 0.f;
#pragma unroll
        for (int i = 0; i < 15; i++) {
            const float d = tri[i] - mean;
            var += d * d;
        }
        var += 15.0f * mean * mean;   // 15 zero entries each contribute mean^2
        var *= (1.0f / 30.0f);

        const float inv = 1.0f / (sqrtf(var) + 1e-8f);

        float* o = out + n * 30;
#pragma unroll
        for (int i = 0; i < 15; i++) o[i] = (tri[i] - mean) * inv;
        const float zval = -mean * inv;
#pragma unroll
        for (int i = 15; i < 30; i++) o[i] = zval;
    }
}

extern "C" void kernel_launch(void* const* d_in, const int* in_sizes, int n_in,
                              void* d_out, int out_size) {
    const float* X = (const float*)d_in[0];
    float* out = (float*)d_out;

    const int smem_bytes = NSTAGES * STAGE_BYTES;   // 96 KB
    cudaFuncSetAttribute(ssf_tma_kernel,
                         cudaFuncAttributeMaxDynamicSharedMemorySize,
                         smem_bytes);
    ssf_tma_kernel<<<N_BATCH, THREADS, smem_bytes>>>(X, out);
}